// round 9
// baseline (speedup 1.0000x reference)
#include <cuda_runtime.h>
#include <cuda_bf16.h>
#include <cstdint>

// Problem constants (fixed by setup_inputs)
#define HPM       8
#define NUM_PAGES 4096
#define PAGE_SIZE 16
#define DPM       128
#define MAX_SEQS  8
#define MAX_PPS   256
#define D4        (DPM / 4)                                    // 32 float4 per row
#define PAGES_ELEMS (2LL * HPM * NUM_PAGES * PAGE_SIZE * DPM)  // 134,217,728 floats
#define INNER_F4  (HPM * NUM_PAGES * PAGE_SIZE * D4)           // 1<<24 float4 per tensor
#define TOTAL_F4  (2u * INNER_F4)                              // 1<<25

// Scratch (device globals — no allocation allowed)
__device__ int g_blk_of_page[NUM_PAGES];   // -1 => keep old contents, else block index
__device__ int g_page_of_block[MAX_PPS];

// ---------------------------------------------------------------------------
// Kernel A (slim, R8-identical): first-fit allocation + both small outputs.
// All global reads issued up-front so their DRAM trips overlap.
// ---------------------------------------------------------------------------
__global__ void __launch_bounds__(256)
setup_kernel(const int* __restrict__ page_indices,
             const int* __restrict__ seq_page_indices,
             const int* __restrict__ slot_p,
             const int* __restrict__ true_length_p,
             float* __restrict__ out_pi,
             float* __restrict__ out_spi)
{
    __shared__ int s_base[8];
    const int tid  = threadIdx.x;
    const int lane = tid & 31;
    const int wrp  = tid >> 5;

    const int4* pi4  = (const int4*)page_indices;
    const int4* spi4 = (const int4*)seq_page_indices;
    int4 pv[4], sv[2];
#pragma unroll
    for (int k = 0; k < 4; k++) pv[k] = __ldg(&pi4[tid * 4 + k]);
#pragma unroll
    for (int k = 0; k < 2; k++) sv[k] = __ldg(&spi4[tid * 2 + k]);
    const int tl   = __ldg(true_length_p);
    const int slot = __ldg(slot_p);

    int vals[16], fl[16];
    int cnt = 0;
#pragma unroll
    for (int k = 0; k < 4; k++) {
        vals[k*4+0] = pv[k].x; vals[k*4+1] = pv[k].y;
        vals[k*4+2] = pv[k].z; vals[k*4+3] = pv[k].w;
    }
#pragma unroll
    for (int j = 0; j < 16; j++) {
        int p = tid * 16 + j;
        fl[j] = (p >= 1) && (vals[j] == 0);
        cnt += fl[j];
    }

    int incl = cnt;
#pragma unroll
    for (int off = 1; off < 32; off <<= 1) {
        int n = __shfl_up_sync(0xffffffffu, incl, off);
        if (lane >= off) incl += n;
    }
    if (lane == 31) s_base[wrp] = incl;
    __syncthreads();

    if (wrp == 0 && lane < 8) {
        int v = s_base[lane];
        int s = v;
#pragma unroll
        for (int off = 1; off < 8; off <<= 1) {
            int n = __shfl_up_sync(0xffu, s, off);
            if (lane >= off) s += n;
        }
        s_base[lane] = s - v;
    }
    __syncthreads();

    const int excl = s_base[wrp] + (incl - cnt);

    int nb = (tl + PAGE_SIZE - 1) / PAGE_SIZE;
    if (nb > MAX_PPS) nb = MAX_PPS;

    int run = excl;
    float pi_out[16];
#pragma unroll
    for (int j = 0; j < 16; j++) {
        int p = tid * 16 + j;
        int b = -1;
        if (fl[j]) {
            if (run < nb) { b = run; g_page_of_block[run] = p; }
            run++;
        }
        g_blk_of_page[p] = b;
        pi_out[j] = (b >= 0) ? 1.0f : (float)vals[j];
    }

#pragma unroll
    for (int k = 0; k < 4; k++) {
        float4 v = make_float4(pi_out[k*4+0], pi_out[k*4+1], pi_out[k*4+2], pi_out[k*4+3]);
        ((float4*)out_pi)[tid * 4 + k] = v;
    }

    __syncthreads();   // g_page_of_block visible block-wide

    int svals[8] = { sv[0].x, sv[0].y, sv[0].z, sv[0].w,
                     sv[1].x, sv[1].y, sv[1].z, sv[1].w };
#pragma unroll
    for (int j = 0; j < 8; j++) {
        int i = tid * 8 + j;
        int r = i >> 8, c = i & 255;
        float v = (float)svals[j];
        if (r == slot && c < nb) v = (float)g_page_of_block[c];
        out_spi[i] = v;
    }
}

// ---------------------------------------------------------------------------
// Kernel B: assemble [2, H, P, PS, D]. Block covers 2048 f4, processed as
// two groups of 4 independent float4 (load4 -> store4 -> load4 -> store4).
// Stores are issue-and-forget, so group 2's loads overlap group 1's drain:
// up to 8 requests in flight per thread with group-1 register reuse.
// ---------------------------------------------------------------------------
__global__ void __launch_bounds__(256)
assemble_pages_kernel(const float4* __restrict__ key,        // [1, S, H, D]
                      const float4* __restrict__ value,
                      const float4* __restrict__ key_pages,  // [H, P, PS, D]
                      const float4* __restrict__ value_pages,
                      float4* __restrict__ out)               // [2, H, P, PS, D]
{
    const unsigned base0 = blockIdx.x * 2048u + threadIdx.x;  // block covers 2048 f4
    const unsigned t = base0 >> 24;                            // 0 = key, 1 = value (uniform)
    const float4* __restrict__ kv    = t ? value       : key;
    const float4* __restrict__ pages = t ? value_pages : key_pages;

#pragma unroll
    for (int g = 0; g < 2; g++) {
        const unsigned base = base0 + g * 1024u;

        const float4* srcs[4];
#pragma unroll
        for (int j = 0; j < 4; j++) {
            unsigned idx = base + j * 256u;
            unsigned v   = idx;
            unsigned d4  = v & (D4 - 1);        v >>= 5;
            unsigned row = v & (PAGE_SIZE - 1); v >>= 4;
            unsigned p   = v & (NUM_PAGES - 1); v >>= 12;
            unsigned h   = v & (HPM - 1);

            int b = g_blk_of_page[p];            // warp-uniform (16KB, L2-resident)
            unsigned s    = (unsigned)b * PAGE_SIZE + row;
            unsigned offA = (s * HPM + h) * D4 + d4;        // key/value (transpose folded)
            unsigned offB = idx & (INNER_F4 - 1);           // pass-through pages
            srcs[j] = (b >= 0) ? (kv + offA) : (pages + offB);
        }

        float4 vals[4];
#pragma unroll
        for (int j = 0; j < 4; j++) vals[j] = __ldcs(srcs[j]);   // 4 back-to-back LDG.128.CS

#pragma unroll
        for (int j = 0; j < 4; j++) __stcs(&out[base + j * 256u], vals[j]);
    }
}

// ---------------------------------------------------------------------------
// Launch — two plain kernel nodes.
// Inputs: key, value, key_pages, value_pages, page_indices, seq_page_indices,
//         slot, true_length
// Output: concat(pages[2,H,P,PS,D], page_indices[4096], seq_page_indices[2048])
// ---------------------------------------------------------------------------
extern "C" void kernel_launch(void* const* d_in, const int* in_sizes, int n_in,
                              void* d_out, int out_size)
{
    const float* key          = (const float*)d_in[0];
    const float* value        = (const float*)d_in[1];
    const float* key_pages    = (const float*)d_in[2];
    const float* value_pages  = (const float*)d_in[3];
    const int*   page_indices = (const int*)d_in[4];
    const int*   seq_page_ind = (const int*)d_in[5];
    const int*   slot         = (const int*)d_in[6];
    const int*   true_length  = (const int*)d_in[7];

    float* out_pages = (float*)d_out;
    float* out_pi    = out_pages + PAGES_ELEMS;
    float* out_spi   = out_pi + NUM_PAGES;

    setup_kernel<<<1, 256>>>(page_indices, seq_page_ind, slot, true_length,
                             out_pi, out_spi);

    assemble_pages_kernel<<<TOTAL_F4 / 2048u, 256>>>(
        (const float4*)key, (const float4*)value,
        (const float4*)key_pages, (const float4*)value_pages,
        (float4*)out_pages);
}